// round 17
// baseline (speedup 1.0000x reference)
#include <cuda_runtime.h>
#include <cuda_fp16.h>
#include <cstdint>
#include <math.h>

#define BATCH_ 4096
#define HID_   2048
#define KTOT   4096            // K = INPUT(2048 from x) ++ HIDDEN(2048 from h)
#define BH     ((size_t)BATCH_ * HID_)

// CTA = 64(m) x [32(n) x 4 gates](128 B-rows) x 32(k); 4 warps; warp == gate,
// warp tile 64m x 32n. 4-stage ring, lookahead 2, 4 CTAs/SM.
#define BM 64
#define BK 32
#define STAGES 4
#define NKC (KTOT / BK)        // 128 k-iterations

// SMEM stage layout (12KB per stage, 4 stages = 48KB -> 4 CTAs/SM)
#define OFF_A  0
#define OFF_B  4096
#define ST_BYTES 12288
#define SMEM_TOTAL (STAGES * ST_BYTES)

// Epilogue exchange layout (reuses stage smem after the mainloop; 34.5KB <= 48KB)
#define EPSS     133                    // floats per m-row (odd -> conflict-free)
#define BIAS_OFF (64 * EPSS)            // 128 bias floats after the 64-row tile

// ---------------- scratch (device globals; allocation-free) ----------------
__device__ __half g_A[(size_t)BATCH_ * KTOT];      // [b][k] f16          32MB
__device__ __half g_B[(size_t)4 * HID_ * KTOT];    // [g*2048+n][k] f16   64MB

// ---------------- PTX helpers (base ISA only) ----------------
__device__ __forceinline__ uint32_t smem_u32(const void* p) {
    uint32_t a;
    asm("{ .reg .u64 t; cvta.to.shared.u64 t, %1; cvt.u32.u64 %0, t; }" : "=r"(a) : "l"(p));
    return a;
}
__device__ __forceinline__ void cp16(uint32_t dst, const void* src) {
    asm volatile("cp.async.cg.shared.global [%0], [%1], 16;" :: "r"(dst), "l"(src));
}
__device__ __forceinline__ void cp_commit() { asm volatile("cp.async.commit_group;" ::: "memory"); }
template <int N>
__device__ __forceinline__ void cp_wait() { asm volatile("cp.async.wait_group %0;" :: "n"(N) : "memory"); }

__device__ __forceinline__ void ldsm4(uint32_t* r, uint32_t addr) {
    asm volatile("ldmatrix.sync.aligned.m8n8.x4.shared.b16 {%0,%1,%2,%3}, [%4];"
                 : "=r"(r[0]), "=r"(r[1]), "=r"(r[2]), "=r"(r[3]) : "r"(addr));
}
__device__ __forceinline__ void mma16816(float* d, const uint32_t* a, uint32_t b0, uint32_t b1) {
    asm volatile(
        "mma.sync.aligned.m16n8k16.row.col.f32.f16.f16.f32 "
        "{%0,%1,%2,%3}, {%4,%5,%6,%7}, {%8,%9}, {%0,%1,%2,%3};"
        : "+f"(d[0]), "+f"(d[1]), "+f"(d[2]), "+f"(d[3])
        : "r"(a[0]), "r"(a[1]), "r"(a[2]), "r"(a[3]), "r"(b0), "r"(b1));
}

// 64B-row swizzle (proven R10/R11): 16B-column k2 XOR (row>>1)&3.
// Row steps of 16/32 preserve (row>>1)&3 -> constant strides. ko-step == ^(ko<<5).
__device__ __forceinline__ uint32_t sw64(int row, int k2) {
    return (uint32_t)(row * 64 + ((k2 ^ ((row >> 1) & 3)) << 4));
}

// ---------------- merged conversion kernel (proven R14-R16) ----------------
__global__ __launch_bounds__(256) void conv_kernel(
    const float* __restrict__ x, const float* __restrict__ h,
    const float* __restrict__ w_ih, const float* __restrict__ w_hh)
{
    if (blockIdx.z == 0) {
        const int bid = blockIdx.y * 64 + blockIdx.x;            // 0..8191
        const size_t e = ((size_t)bid * 256 + threadIdx.x) * 4;  // < 4096*2048
        const int row = (int)(e >> 11);
        const int col = (int)(e & 2047);
        const float4 xv = *reinterpret_cast<const float4*>(x + e);
        const float4 hv = *reinterpret_cast<const float4*>(h + e);
        const size_t base = (size_t)row * KTOT + col;
        __half2* a0 = reinterpret_cast<__half2*>(g_A + base);
        __half2* a1 = reinterpret_cast<__half2*>(g_A + base + 2048);
        a0[0] = __floats2half2_rn(xv.x, xv.y);
        a0[1] = __floats2half2_rn(xv.z, xv.w);
        a1[0] = __floats2half2_rn(hv.x, hv.y);
        a1[1] = __floats2half2_rn(hv.z, hv.w);
    } else {
        __shared__ float t[32][33];
        const int g = blockIdx.z - 1;
        const int nt = blockIdx.x * 32;      // 64 blocks * 32 = 2048
        const int kt = blockIdx.y * 32;      // 128 blocks * 32 = 4096
        const int tx = threadIdx.x & 31;
        const int ty = threadIdx.x >> 5;     // 0..7
#pragma unroll
        for (int r = 0; r < 4; r++) {
            const int kk = kt + ty + r * 8;
            const float* src = (kk < 2048)
                ? (w_ih + ((size_t)g * 2048 + kk) * HID_)
                : (w_hh + ((size_t)g * 2048 + (kk - 2048)) * HID_);
            t[ty + r * 8][tx] = src[nt + tx];
        }
        __syncthreads();
#pragma unroll
        for (int r = 0; r < 4; r++) {
            const int nn = nt + ty + r * 8;
            g_B[((size_t)g * HID_ + nn) * KTOT + kt + tx] =
                __float2half_rn(t[tx][ty + r * 8]);
        }
    }
}

// ---------------- fused f16 GEMM + LSTM epilogue (128 thr, 4 CTAs/SM) ----------------
__device__ __forceinline__ float sigmoid_f(float v) { return 1.0f / (1.0f + expf(-v)); }

__global__ __launch_bounds__(128, 4) void lstm_fused_kernel(
    const float* __restrict__ cprev, const float* __restrict__ b_ih,
    const float* __restrict__ b_hh, float* __restrict__ out)
{
    extern __shared__ char smem[];
    const uint32_t sb = smem_u32(smem);
    const int tid = threadIdx.x;
    const int wc = tid >> 5;       // warp == gate index, 0..3
    const int lid = tid & 31;
    const int m0 = blockIdx.x * BM;
    const int n0 = blockIdx.y * 32;     // 32 hidden cols per CTA

    // ---- producer constants (row steps of 32 preserve swizzle phase) ----
    // A stage: 64 rows x 4 k2 = 256 x 16B -> 2 chunks/thread (rows +32)
    // B stage: 128 rows x 4  = 512 x 16B -> 4 chunks/thread (j == gate, rows r0)
    const int pr = tid >> 2;            // 0..31 (base row)
    const int pk = tid & 3;             // 16B column 0..3
    const uint32_t oA0 = sw64(pr, pk);                 // + j*2048 (j=0,1)
    const uint32_t oB0 = (uint32_t)OFF_B + oA0;        // + j*2048 (j=0..3)
    const size_t gA0 = (size_t)(m0 + pr) * KTOT + pk * 8;     // + j*32*KTOT
    const size_t gB0 = (size_t)(n0 + pr) * KTOT + pk * 8;     // + j*HID*KTOT

    // ---- consumer ldmatrix offsets (i/nt step +16 rows = +1024B; ko-step ^(ko<<5)) ----
    const uint32_t aOff0 = sw64(lid & 15, lid >> 4);                        // + i*1024
    const uint32_t bOff0 = (uint32_t)OFF_B + sw64(wc * 32 + (lid & 15), lid >> 4); // + nt*1024

    float acc[4][4][4];
#pragma unroll
    for (int i = 0; i < 4; i++)
#pragma unroll
        for (int j = 0; j < 4; j++)
#pragma unroll
            for (int p = 0; p < 4; p++) acc[i][j][p] = 0.0f;

    auto load_stage = [&](int kt, int st) {
        const uint32_t base = sb + (uint32_t)st * ST_BYTES;
        const int k0 = kt * BK;
#pragma unroll
        for (int j = 0; j < 2; j++)
            cp16(base + OFF_A + oA0 + j * 2048u,
                 g_A + gA0 + (size_t)j * 32 * KTOT + k0);
#pragma unroll
        for (int j = 0; j < 4; j++)
            cp16(base + oB0 + j * 2048u,
                 g_B + gB0 + (size_t)j * HID_ * KTOT + k0);
    };

    load_stage(0, 0); cp_commit();
    load_stage(1, 1); cp_commit();
    load_stage(2, 2); cp_commit();

    for (int kt = 0; kt < NKC; kt++) {
        cp_wait<STAGES - 2>();          // stage kt's group retired (lookahead 2)
        __syncthreads();                // kt visible; all warps past kt-1 (slot reuse safe)

        const int np = kt + STAGES - 1; // prefetch 3 ahead into slot (kt+3)&3
        if (np < NKC) load_stage(np, np & (STAGES - 1));
        cp_commit();                    // (possibly empty) keeps group counts aligned

        const uint32_t base = sb + (uint32_t)(kt & (STAGES - 1)) * ST_BYTES;

#pragma unroll
        for (int ko = 0; ko < 2; ko++) {           // two k16 steps per k32 stage
            const uint32_t kx = (uint32_t)ko << 5;
            uint32_t a[4][4], b[2][4];
#pragma unroll
            for (int i = 0; i < 4; i++)
                ldsm4(a[i], base + ((aOff0 + i * 1024u) ^ kx));
#pragma unroll
            for (int nt = 0; nt < 2; nt++)
                ldsm4(b[nt], base + ((bOff0 + nt * 1024u) ^ kx));
#pragma unroll
            for (int nt = 0; nt < 2; nt++)
#pragma unroll
                for (int i = 0; i < 4; i++) {
                    mma16816(acc[i][2 * nt],     a[i], b[nt][0], b[nt][2]);
                    mma16816(acc[i][2 * nt + 1], a[i], b[nt][1], b[nt][3]);
                }
        }
    }

    // ---------------- fused epilogue: exchange via smem, then pointwise ----------------
    cp_wait<0>();
    __syncthreads();
    float* eps = reinterpret_cast<float*>(smem);

    // store accumulators: eps[row][gate*32 + col]  (wc == gate; rows 0..63)
#pragma unroll
    for (int i = 0; i < 4; i++) {
        const int r0 = i * 16 + (lid >> 2);
        const int r1 = r0 + 8;
#pragma unroll
        for (int n8 = 0; n8 < 4; n8++) {
            const int coloff = wc * 32 + n8 * 8 + (lid & 3) * 2;
            eps[r0 * EPSS + coloff]     = acc[i][n8][0];
            eps[r0 * EPSS + coloff + 1] = acc[i][n8][1];
            eps[r1 * EPSS + coloff]     = acc[i][n8][2];
            eps[r1 * EPSS + coloff + 1] = acc[i][n8][3];
        }
    }
    // bias sums: 4 gates x 32 cols (exactly 128 threads)
    {
        const int g = tid >> 5, cc = tid & 31;
        eps[BIAS_OFF + tid] = b_ih[g * HID_ + n0 + cc] + b_hh[g * HID_ + n0 + cc];
    }
    __syncthreads();

    // 4 passes: 16 rows x (8 lanes * 4 cols = 32 cols); 128B-contiguous global writes
#pragma unroll 1
    for (int p = 0; p < 4; p++) {
        const int row = (tid >> 3) + p * 16;
        const int ct  = (tid & 7) * 4;
        const float* er = eps + row * EPSS;
        const size_t gbase = (size_t)(m0 + row) * HID_ + n0 + ct;
        const float4 cv = *reinterpret_cast<const float4*>(cprev + gbase);
        float4 hn, cn;
#pragma unroll
        for (int j = 0; j < 4; j++) {
            const int cc = ct + j;
            const float gi = er[cc]      + eps[BIAS_OFF + cc];
            const float gf = er[32 + cc] + eps[BIAS_OFF + 32 + cc];
            const float gc = er[64 + cc] + eps[BIAS_OFF + 64 + cc];
            const float go = er[96 + cc] + eps[BIAS_OFF + 96 + cc];
            const float ig = sigmoid_f(gi);
            const float fg = sigmoid_f(gf);
            const float cg = tanhf(gc);
            const float og = sigmoid_f(go);
            const float cpv = (j == 0) ? cv.x : (j == 1) ? cv.y : (j == 2) ? cv.z : cv.w;
            const float cnv = fg * cpv + ig * cg;
            const float hnv = og * tanhf(cnv);
            if (j == 0) { hn.x = hnv; cn.x = cnv; }
            else if (j == 1) { hn.y = hnv; cn.y = cnv; }
            else if (j == 2) { hn.z = hnv; cn.z = cnv; }
            else { hn.w = hnv; cn.w = cnv; }
        }
        *reinterpret_cast<float4*>(out + gbase)      = hn;
        *reinterpret_cast<float4*>(out + BH + gbase) = cn;
    }
}

// ---------------- launch ----------------
extern "C" void kernel_launch(void* const* d_in, const int* in_sizes, int n_in,
                              void* d_out, int out_size)
{
    (void)in_sizes; (void)n_in; (void)out_size;
    const float* x    = (const float*)d_in[0];
    const float* h    = (const float*)d_in[1];
    const float* c    = (const float*)d_in[2];
    const float* w_ih = (const float*)d_in[3];
    const float* w_hh = (const float*)d_in[4];
    const float* b_ih = (const float*)d_in[5];
    const float* b_hh = (const float*)d_in[6];
    float* out = (float*)d_out;

    // 1) merged conversion: z=0 -> A f16, z=1..4 -> weight transpose f16
    conv_kernel<<<dim3(64, 128, 5), 256>>>(x, h, w_ih, w_hh);

    // 2) fused f16 GEMM + LSTM epilogue, 128-thread CTAs, 4-stage ring, 4 CTAs/SM
    //    (m-fastest grid for B-panel L2 reuse)
    cudaFuncSetAttribute(lstm_fused_kernel,
                         cudaFuncAttributeMaxDynamicSharedMemorySize, SMEM_TOTAL);
    dim3 gg(BATCH_ / BM, HID_ / 32);   // (64, 64)
    lstm_fused_kernel<<<gg, 128, SMEM_TOTAL>>>(c, b_ih, b_hh, out);
}